// round 1
// baseline (speedup 1.0000x reference)
#include <cuda_runtime.h>

#define HH 128
#define WW 128
#define NP 2048
#define DIMU 768
#define PTOT (HH*WW)

// ---- scratch (device globals: no allocation allowed) ----
__device__ __align__(16) float4 g_pA[NP];   // gx, gy, rx, ry   (rx<0 => culled)
__device__ __align__(16) float4 g_pB[NP];   // 0.5A, B, 0.5C, smax
__device__ __align__(16) float4 g_pC[NP];   // cr, cg, cb, opacity
__device__ __align__(16) float  g_imr[PTOT];
__device__ __align__(16) float  g_img[PTOT];
__device__ __align__(16) float  g_imb[PTOT];

// ============================================================
// K1: per-gaussian preprocess (N=2048)
// ============================================================
__global__ void k_pre(const float* __restrict__ xyz,
                      const float* __restrict__ scaling,
                      const float* __restrict__ rotation,
                      const float* __restrict__ features,
                      const float* __restrict__ opacity) {
    int n = blockIdx.x * blockDim.x + threadIdx.x;
    if (n >= NP) return;

    float mx = tanhf(xyz[2*n + 0]);
    float my = tanhf(xyz[2*n + 1]);
    float s0 = fabsf(scaling[2*n + 0] + 0.5f);
    float s1 = fabsf(scaling[2*n + 1] + 0.5f);
    float th = (1.0f / (1.0f + expf(-rotation[n]))) * 6.283185307179586f;
    float c  = cosf(th), sn = sinf(th);
    float a = c * s0, b = -sn * s1, d = sn * s0, e = c * s1;
    float cxx = a*a + b*b;
    float cxy = a*d + b*e;
    float cyy = d*d + e*e;
    float det = cxx*cyy - cxy*cxy;
    float A =  cyy / det;
    float B = -cxy / det;
    float C =  cxx / det;
    float gx = 0.5f * (mx + 1.0f) * (float)WW;
    float gy = 0.5f * (my + 1.0f) * (float)HH;
    float op = opacity[n];
    float smax = logf(255.0f * op);   // alpha >= 1/255  <=>  sigma <= smax

    float rx, ry;
    if (smax > 0.0f && det > 0.0f) {
        // exact per-axis extent of {sigma<=smax}: rx = sqrt(2*smax*cov_xx); pad conservatively
        rx = sqrtf(2.0f * smax * cxx) * 1.001f + 0.02f;
        ry = sqrtf(2.0f * smax * cyy) * 1.001f + 0.02f;
    } else {
        rx = -1.0f; ry = -1.0f; smax = -1.0f;
    }
    g_pA[n] = make_float4(gx, gy, rx, ry);
    g_pB[n] = make_float4(0.5f * A, B, 0.5f * C, smax);
    g_pC[n] = make_float4(features[3*n+0], features[3*n+1], features[3*n+2], op);
}

// ============================================================
// K2: tiled rasterizer. 16x16 pixel tile per block, 256 thr.
// Chunked cull+compact into smem, then branch-free accumulate.
// ============================================================
__global__ void k_raster() {
    __shared__ float4 sA[256];
    __shared__ float4 sB[256];
    __shared__ float4 sC[256];
    __shared__ int s_cnt;

    int tid = threadIdx.x;
    int tx = tid & 15, ty = tid >> 4;
    int x0 = blockIdx.x * 16, y0 = blockIdx.y * 16;
    float px = (float)(x0 + tx) + 0.5f;
    float py = (float)(y0 + ty) + 0.5f;
    float txmin = (float)x0 + 0.5f, txmax = (float)x0 + 15.5f;
    float tymin = (float)y0 + 0.5f, tymax = (float)y0 + 15.5f;

    float accr = 0.0f, accg = 0.0f, accb = 0.0f;

    #pragma unroll 1
    for (int base = 0; base < NP; base += 256) {
        if (tid == 0) s_cnt = 0;
        __syncthreads();
        int gi = base + tid;                    // NP % 256 == 0
        float4 a = g_pA[gi];
        if (a.z >= 0.0f &&
            a.x + a.z >= txmin && a.x - a.z <= txmax &&
            a.y + a.w >= tymin && a.y - a.w <= tymax) {
            int pos = atomicAdd(&s_cnt, 1);
            sA[pos] = a;
            sB[pos] = g_pB[gi];
            sC[pos] = g_pC[gi];
        }
        __syncthreads();
        int cnt = s_cnt;
        for (int j = 0; j < cnt; j++) {
            float4 pa = sA[j];
            float4 pb = sB[j];
            float4 pc = sC[j];
            float dx = pa.x - px;
            float dy = pa.y - py;
            float sig = pb.x * dx * dx + pb.z * dy * dy + pb.y * dx * dy;
            float al = fminf(0.999f, pc.w * __expf(-sig));
            al = (sig >= 0.0f && al >= (1.0f / 255.0f)) ? al : 0.0f;
            accr += al * pc.x;
            accg += al * pc.y;
            accb += al * pc.z;
        }
        __syncthreads();
    }

    int p = (y0 + ty) * WW + (x0 + tx);
    g_imr[p] = fminf(1.0f, fmaxf(0.0f, accr));
    g_img[p] = fminf(1.0f, fmaxf(0.0f, accg));
    g_imb[p] = fminf(1.0f, fmaxf(0.0f, accb));
}

// ============================================================
// K3: up-projection + transposed write.
// Block = (1024 pixels) x (24 output dims). Pixels live in
// registers (float4 per thread); 24 coalesced STG.128 sweeps.
// ============================================================
#define D_BLK 24
__global__ void k_up(const float* __restrict__ w_up,
                     const float* __restrict__ b_up,
                     float* __restrict__ out) {
    int tid = threadIdx.x;                         // 256
    int p4  = blockIdx.x * 256 + tid;              // float4 pixel index, [0, 4096)
    int db  = blockIdx.y * D_BLK;

    float4 R = ((const float4*)g_imr)[p4];
    float4 G = ((const float4*)g_img)[p4];
    float4 B = ((const float4*)g_imb)[p4];
    float4* out4 = (float4*)out;

    #pragma unroll
    for (int i = 0; i < D_BLK; i++) {
        int d = db + i;
        float wr = __ldg(&w_up[3*d + 0]);
        float wg = __ldg(&w_up[3*d + 1]);
        float wb = __ldg(&w_up[3*d + 2]);
        float bb = __ldg(&b_up[d]);
        float4 o;
        o.x = bb + R.x * wr + G.x * wg + B.x * wb;
        o.y = bb + R.y * wr + G.y * wg + B.y * wb;
        o.z = bb + R.z * wr + G.z * wg + B.z * wb;
        o.w = bb + R.w * wr + G.w * wg + B.w * wb;
        out4[(size_t)d * (PTOT / 4) + p4] = o;
    }
}

// ============================================================
extern "C" void kernel_launch(void* const* d_in, const int* in_sizes, int n_in,
                              void* d_out, int out_size) {
    // metadata order: x, xyz, scaling, rotation, features, opacity, w_up, b_up
    const float* xyz      = (const float*)d_in[1];
    const float* scaling  = (const float*)d_in[2];
    const float* rotation = (const float*)d_in[3];
    const float* features = (const float*)d_in[4];
    const float* opacity  = (const float*)d_in[5];
    const float* w_up     = (const float*)d_in[6];
    const float* b_up     = (const float*)d_in[7];
    float* out = (float*)d_out;

    k_pre<<<(NP + 255) / 256, 256>>>(xyz, scaling, rotation, features, opacity);
    k_raster<<<dim3(WW / 16, HH / 16), 256>>>();
    k_up<<<dim3(PTOT / 1024, DIMU / D_BLK), 256>>>(w_up, b_up, out);
}